// round 7
// baseline (speedup 1.0000x reference)
#include <cuda_runtime.h>
#include <cuda_bf16.h>

__device__ __forceinline__ float tanh_(float x){ float y; asm("tanh.approx.f32 %0, %1;" : "=f"(y) : "f"(x)); return y; }
__device__ __forceinline__ float ex2_(float x) { float y; asm("ex2.approx.f32 %0, %1;" : "=f"(y) : "f"(x)); return y; }
__device__ __forceinline__ float lg2_(float x) { float y; asm("lg2.approx.f32 %0, %1;" : "=f"(y) : "f"(x)); return y; }
__device__ __forceinline__ float sig_(float x) { return __frcp_rn(1.0f + ex2_(-1.44269504f * x)); }

// 32 CTAs x 1024 threads, clusters of 2. Each CTA computes HALF the h-range of
// the (input-independent) s_t table; halves are summed via DSMEM after a cheap
// cluster barrier (~380cyc, vs ~2us for the R3 global atomic barrier).
__global__ void __launch_bounds__(1024, 1) __cluster_dims__(2, 1, 1)
qlstm_all(const int*   __restrict__ x,    // (1024,128)
          const float* __restrict__ qw,   // (4,2,8)
          const float* __restrict__ Wo,   // (4,256,8)
          const float* __restrict__ bo,   // (4,256)
          const float* __restrict__ fcW,  // (2,256)
          const float* __restrict__ fcb,  // (2,)
          float*       __restrict__ out)  // (1024,2)
{
    const int tid  = threadIdx.x;
    const int lane = tid & 31;
    const int wrp  = tid >> 5;
    const int row  = blockIdx.x * 32 + wrp;      // this warp's batch row

    unsigned rank;
    asm("mov.u32 %0, %%cluster_ctarank;" : "=r"(rank));
    const int h_base = (int)rank * 128;          // this CTA's h half

    // Prefetch mask slice immediately.
    const int4 px = *(const int4*)(x + row * 128 + lane * 4);

    __shared__ float  zeta_s[32];
    __shared__ float  zz[32];                    // CNOT-ring Heisenberg Z-products
    __shared__ float4 pA[128];                   // (f, ig, A=ig/(1-f), log2 f) for local h
    __shared__ float2 pB[128];                   // (oo*fcW0, oo*fcW1)
    __shared__ float2 sp[128];                   // local-half partial s_t (peer reads this)
    __shared__ float2 sf[128];                   // full s_t

    // zeta[g][j] = -sin(qw[g,0,j])  (H->RX global phase; RZ drops out)
    if (tid < 32) {
        int g = tid >> 3, j = tid & 7;
        zeta_s[tid] = -__sinf(qw[g * 16 + j]);
    }
    __syncwarp();
    if (tid < 32) {
        int g = tid >> 3, w = tid & 7;
        float p = 1.0f;
        if (w == 0) { for (int j = 1; j < 8; j++)  p *= zeta_s[g * 8 + j]; }
        else        { for (int j = 0; j <= w; j++) p *= zeta_s[g * 8 + j]; }
        zz[tid] = p;
    }
    __syncthreads();

    // Gate params for this CTA's 128 h's (threads 0..127)
    if (tid < 128) {
        const int h = h_base + tid;
        float pre[4];
#pragma unroll
        for (int g = 0; g < 4; g++) {
            const float4* wp = (const float4*)(Wo + (g * 256 + h) * 8);
            float4 wa = wp[0], wb = wp[1];
            const float* z = &zz[g * 8];
            pre[g] = bo[g * 256 + h]
                   + wa.x * z[0] + wa.y * z[1] + wa.z * z[2] + wa.w * z[3]
                   + wb.x * z[4] + wb.y * z[5] + wb.z * z[6] + wb.w * z[7];
        }
        const float e   = ex2_(-1.44269504f * pre[0]);
        const float ope = 1.0f + e;
        const float f_  = __frcp_rn(ope);            // sigmoid(pre0)
        const float lf2 = -lg2_(ope);                // log2(f)
        const float ig_ = sig_(pre[1]) * tanh_(pre[2]);
        const float oo_ = sig_(pre[3]);
        const float omf = __fdividef(e, ope);        // 1 - f
        const float A_  = ig_ * __frcp_rn(omf);      // c_inf
        pA[tid] = make_float4(f_, ig_, A_, lf2);
        pB[tid] = make_float2(oo_ * fcW[h], oo_ * fcW[256 + h]);
    }
    __syncthreads();

    // Sweep: warp w owns t in [4w,4w+4); lane owns local h in [4l,4l+4).
    // Closed-form jump c_{4w} = A(1-f^{4w}), then 4 exact recursion steps.
    {
        const float n0 = (float)(4 * wrp);
        float a00 = 0.f, a01 = 0.f, a02 = 0.f, a03 = 0.f;   // class 0, t..t+3
        float a10 = 0.f, a11 = 0.f, a12 = 0.f, a13 = 0.f;   // class 1
#pragma unroll
        for (int k = 0; k < 4; k++) {
            const int hl = lane * 4 + k;
            const float4 P = pA[hl];
            const float2 Q = pB[hl];
            float c = P.z - P.z * ex2_(n0 * P.w);
            float th;
            c = fmaf(P.x, c, P.y); th = tanh_(c); a00 += Q.x * th; a10 += Q.y * th;
            c = fmaf(P.x, c, P.y); th = tanh_(c); a01 += Q.x * th; a11 += Q.y * th;
            c = fmaf(P.x, c, P.y); th = tanh_(c); a02 += Q.x * th; a12 += Q.y * th;
            c = fmaf(P.x, c, P.y); th = tanh_(c); a03 += Q.x * th; a13 += Q.y * th;
        }
        // Butterfly: sum each accumulator over the 32 lanes (h-reduction)
#pragma unroll
        for (int off = 16; off; off >>= 1) {
            a00 += __shfl_xor_sync(0xffffffffu, a00, off);
            a01 += __shfl_xor_sync(0xffffffffu, a01, off);
            a02 += __shfl_xor_sync(0xffffffffu, a02, off);
            a03 += __shfl_xor_sync(0xffffffffu, a03, off);
            a10 += __shfl_xor_sync(0xffffffffu, a10, off);
            a11 += __shfl_xor_sync(0xffffffffu, a11, off);
            a12 += __shfl_xor_sync(0xffffffffu, a12, off);
            a13 += __shfl_xor_sync(0xffffffffu, a13, off);
        }
        if (lane == 0) {
            sp[4 * wrp + 0] = make_float2(a00, a10);
            sp[4 * wrp + 1] = make_float2(a01, a11);
            sp[4 * wrp + 2] = make_float2(a02, a12);
            sp[4 * wrp + 3] = make_float2(a03, a13);
        }
    }

    // Cluster barrier #1: both CTAs' partials published (arrive=release).
    asm volatile("barrier.cluster.arrive.aligned;" ::: "memory");
    asm volatile("barrier.cluster.wait.aligned;"   ::: "memory");

    // DSMEM: read peer's partial for t = tid (threads 0..127), sum into sf.
    if (tid < 128) {
        unsigned laddr = (unsigned)__cvta_generic_to_shared(&sp[tid]);
        unsigned raddr;
        asm("mapa.shared::cluster.u32 %0, %1, %2;" : "=r"(raddr) : "r"(laddr), "r"(rank ^ 1u));
        float r0, r1;
        asm volatile("ld.shared::cluster.v2.f32 {%0,%1}, [%2];"
                     : "=f"(r0), "=f"(r1) : "r"(raddr));
        float2 loc = sp[tid];
        sf[tid] = make_float2(loc.x + r0, loc.y + r1);
    }
    // Arrive now (done touching peer smem); defer the wait past stage2 so its
    // latency overlaps the tail. Wait before exit keeps our smem alive for peer.
    asm volatile("barrier.cluster.arrive.aligned;" ::: "memory");
    __syncthreads();

    // Stage 2: masks (in regs since start) x full s table.
    const int tb = lane * 4;
    float a0 = 0.0f, a1 = 0.0f, cnt = 0.0f, m;
    m = (px.x != 0) ? 1.0f : 0.0f; a0 += m * sf[tb + 0].x; a1 += m * sf[tb + 0].y; cnt += m;
    m = (px.y != 0) ? 1.0f : 0.0f; a0 += m * sf[tb + 1].x; a1 += m * sf[tb + 1].y; cnt += m;
    m = (px.z != 0) ? 1.0f : 0.0f; a0 += m * sf[tb + 2].x; a1 += m * sf[tb + 2].y; cnt += m;
    m = (px.w != 0) ? 1.0f : 0.0f; a0 += m * sf[tb + 3].x; a1 += m * sf[tb + 3].y; cnt += m;
#pragma unroll
    for (int off = 16; off; off >>= 1) {
        a0  += __shfl_xor_sync(0xffffffffu, a0, off);
        a1  += __shfl_xor_sync(0xffffffffu, a1, off);
        cnt += __shfl_xor_sync(0xffffffffu, cnt, off);
    }
    if (lane == 0) {
        float inv = __frcp_rn(cnt + 1e-9f);
        float2 o = make_float2(a0 * inv + fcb[0], a1 * inv + fcb[1]);
        *(float2*)(out + row * 2) = o;
    }

    asm volatile("barrier.cluster.wait.aligned;" ::: "memory");
}

extern "C" void kernel_launch(void* const* d_in, const int* in_sizes, int n_in,
                              void* d_out, int out_size)
{
    // metadata order: x, embed, Wi, bi, qw, Wo, bo, fcW, fcb
    const int*   x   = (const int*)  d_in[0];
    const float* qw  = (const float*)d_in[4];
    const float* Wo  = (const float*)d_in[5];
    const float* bo  = (const float*)d_in[6];
    const float* fcW = (const float*)d_in[7];
    const float* fcb = (const float*)d_in[8];
    float* out = (float*)d_out;

    qlstm_all<<<32, 1024>>>(x, qw, Wo, bo, fcW, fcb, out);

    (void)in_sizes; (void)n_in; (void)out_size;
}

// round 8
// speedup vs baseline: 1.2904x; 1.2904x over previous
#include <cuda_runtime.h>
#include <cuda_bf16.h>

__device__ __forceinline__ float tanh_(float x){ float y; asm("tanh.approx.f32 %0, %1;" : "=f"(y) : "f"(x)); return y; }
__device__ __forceinline__ float ex2_(float x) { float y; asm("ex2.approx.f32 %0, %1;" : "=f"(y) : "f"(x)); return y; }
__device__ __forceinline__ float lg2_(float x) { float y; asm("lg2.approx.f32 %0, %1;" : "=f"(y) : "f"(x)); return y; }
__device__ __forceinline__ float sig_(float x) { return __frcp_rn(1.0f + ex2_(-1.44269504f * x)); }

// 32 blocks x 1024 threads, no inter-block communication. Phase chain collapsed
// to 2 syncthreads: [all loads issued at entry || zeta/zz via warp shuffles] ->
// params -> sync -> register-tiled sweep + in-warp butterfly -> sync -> stage2.
__global__ void __launch_bounds__(1024, 1)
qlstm_all(const int*   __restrict__ x,    // (1024,128)
          const float* __restrict__ qw,   // (4,2,8)
          const float* __restrict__ Wo,   // (4,256,8)
          const float* __restrict__ bo,   // (4,256)
          const float* __restrict__ fcW,  // (2,256)
          const float* __restrict__ fcb,  // (2,)
          float*       __restrict__ out)  // (1024,2)
{
    const int tid  = threadIdx.x;
    const int lane = tid & 31;
    const int wrp  = tid >> 5;
    const int row  = blockIdx.x * 32 + wrp;      // this warp's batch row

    __shared__ float4 pA[256];                   // (f, ig, A=ig/(1-f), log2 f)
    __shared__ float2 pB[256];                   // (oo*fcW0, oo*fcW1)
    __shared__ float2 s_s[128];                  // s_t table

    // Mask slice: issue immediately.
    const int4 px = *(const int4*)(x + row * 128 + lane * 4);

    // ---- Param phase: warps 0..7 only (tid < 256 covers them fully, so
    //      full-warp shuffles are legal). All global loads issued FIRST so
    //      their latency overlaps the zeta/zz MUFU+shuffle computation.
    if (tid < 256) {
        const int h = tid;
        // 8x float4 Wo rows + 4x bo + 2x fcW: ~14 outstanding loads
        float4 w0a = ((const float4*)(Wo + (0 * 256 + h) * 8))[0];
        float4 w0b = ((const float4*)(Wo + (0 * 256 + h) * 8))[1];
        float4 w1a = ((const float4*)(Wo + (1 * 256 + h) * 8))[0];
        float4 w1b = ((const float4*)(Wo + (1 * 256 + h) * 8))[1];
        float4 w2a = ((const float4*)(Wo + (2 * 256 + h) * 8))[0];
        float4 w2b = ((const float4*)(Wo + (2 * 256 + h) * 8))[1];
        float4 w3a = ((const float4*)(Wo + (3 * 256 + h) * 8))[0];
        float4 w3b = ((const float4*)(Wo + (3 * 256 + h) * 8))[1];
        float b0 = bo[0 * 256 + h], b1 = bo[1 * 256 + h];
        float b2 = bo[2 * 256 + h], b3 = bo[3 * 256 + h];
        float fc0 = fcW[h], fc1 = fcW[256 + h];

        // zeta[g][j] = -sin(qw[g,0,j])  (H->RX is a global phase; RZ drops)
        // Lane (g=lane>>3, j=lane&7) holds its zeta; CNOT-ring product zz
        // gathered purely with shuffles (overlaps the loads above).
        const int g_ = lane >> 3, j_ = lane & 7;
        const float zeta = -__sinf(qw[g_ * 16 + j_]);
        const int base = lane & 24;              // g*8
        const int w_   = j_;
        float zzv = 1.0f;
#pragma unroll
        for (int j2 = 0; j2 < 8; j2++) {
            float zj = __shfl_sync(0xffffffffu, zeta, base + j2);
            // w==0: product over j2 in [1,7]; w>=1: product over j2 in [0,w]
            bool incl = (w_ == 0) ? (j2 >= 1) : (j2 <= w_);
            zzv = incl ? zzv * zj : zzv;
        }
        // zzv on lane g*8+w  ==  zz[g][w]

        // pre[g] = bo + Wo[g,h,:] . zz[g,:]   (zz gathered by shuffle)
        float pre0 = b0, pre1 = b1, pre2 = b2, pre3 = b3;
#pragma unroll
        for (int q = 0; q < 4; q++) {
            float z0 = __shfl_sync(0xffffffffu, zzv,  0 + q);
            float z4 = __shfl_sync(0xffffffffu, zzv,  4 + q);
            float z8 = __shfl_sync(0xffffffffu, zzv,  8 + q);
            float z12= __shfl_sync(0xffffffffu, zzv, 12 + q);
            float z16= __shfl_sync(0xffffffffu, zzv, 16 + q);
            float z20= __shfl_sync(0xffffffffu, zzv, 20 + q);
            float z24= __shfl_sync(0xffffffffu, zzv, 24 + q);
            float z28= __shfl_sync(0xffffffffu, zzv, 28 + q);
            const float* a;
            a = (const float*)&w0a; pre0 += a[q] * z0;
            a = (const float*)&w0b; pre0 += a[q] * z4;
            a = (const float*)&w1a; pre1 += a[q] * z8;
            a = (const float*)&w1b; pre1 += a[q] * z12;
            a = (const float*)&w2a; pre2 += a[q] * z16;
            a = (const float*)&w2b; pre2 += a[q] * z20;
            a = (const float*)&w3a; pre3 += a[q] * z24;
            a = (const float*)&w3b; pre3 += a[q] * z28;
        }

        const float e   = ex2_(-1.44269504f * pre0);
        const float ope = 1.0f + e;
        const float f_  = __frcp_rn(ope);            // sigmoid(pre0)
        const float lf2 = -lg2_(ope);                // log2(f)
        const float ig_ = sig_(pre1) * tanh_(pre2);
        const float oo_ = sig_(pre3);
        const float omf = __fdividef(e, ope);        // 1 - f
        const float A_  = ig_ * __frcp_rn(omf);      // c_inf
        pA[h] = make_float4(f_, ig_, A_, lf2);
        pB[h] = make_float2(oo_ * fc0, oo_ * fc1);
    }
    __syncthreads();

    // ---- Sweep: warp w owns t in [4w,4w+4); lane owns h in {lane+32k}.
    //      Closed-form jump c_{4w} = A(1-f^{4w}), then 4 exact steps.
    {
        const float n0 = (float)(4 * wrp);
        float a00 = 0.f, a01 = 0.f, a02 = 0.f, a03 = 0.f;   // class 0
        float a10 = 0.f, a11 = 0.f, a12 = 0.f, a13 = 0.f;   // class 1
#pragma unroll
        for (int k = 0; k < 8; k++) {
            const int h = lane + 32 * k;
            const float4 P = pA[h];
            const float2 Q = pB[h];
            float c = P.z - P.z * ex2_(n0 * P.w);
            float th;
            c = fmaf(P.x, c, P.y); th = tanh_(c); a00 += Q.x * th; a10 += Q.y * th;
            c = fmaf(P.x, c, P.y); th = tanh_(c); a01 += Q.x * th; a11 += Q.y * th;
            c = fmaf(P.x, c, P.y); th = tanh_(c); a02 += Q.x * th; a12 += Q.y * th;
            c = fmaf(P.x, c, P.y); th = tanh_(c); a03 += Q.x * th; a13 += Q.y * th;
        }
        // In-warp butterfly: h-reduction across the 32 lanes
#pragma unroll
        for (int off = 16; off; off >>= 1) {
            a00 += __shfl_xor_sync(0xffffffffu, a00, off);
            a01 += __shfl_xor_sync(0xffffffffu, a01, off);
            a02 += __shfl_xor_sync(0xffffffffu, a02, off);
            a03 += __shfl_xor_sync(0xffffffffu, a03, off);
            a10 += __shfl_xor_sync(0xffffffffu, a10, off);
            a11 += __shfl_xor_sync(0xffffffffu, a11, off);
            a12 += __shfl_xor_sync(0xffffffffu, a12, off);
            a13 += __shfl_xor_sync(0xffffffffu, a13, off);
        }
        if (lane == 0) {
            s_s[4 * wrp + 0] = make_float2(a00, a10);
            s_s[4 * wrp + 1] = make_float2(a01, a11);
            s_s[4 * wrp + 2] = make_float2(a02, a12);
            s_s[4 * wrp + 3] = make_float2(a03, a13);
        }
    }
    __syncthreads();

    // ---- Stage 2: masks (in regs since start) x s table (vectorized LDS).
    const float4* st = (const float4*)s_s;           // (s_t, s_{t+1}) per float4
    float4 sa = st[lane * 2 + 0];
    float4 sb = st[lane * 2 + 1];
    float a0 = 0.0f, a1 = 0.0f, cnt = 0.0f, m;
    m = (px.x != 0) ? 1.0f : 0.0f; a0 += m * sa.x; a1 += m * sa.y; cnt += m;
    m = (px.y != 0) ? 1.0f : 0.0f; a0 += m * sa.z; a1 += m * sa.w; cnt += m;
    m = (px.z != 0) ? 1.0f : 0.0f; a0 += m * sb.x; a1 += m * sb.y; cnt += m;
    m = (px.w != 0) ? 1.0f : 0.0f; a0 += m * sb.z; a1 += m * sb.w; cnt += m;
#pragma unroll
    for (int off = 16; off; off >>= 1) {
        a0  += __shfl_xor_sync(0xffffffffu, a0, off);
        a1  += __shfl_xor_sync(0xffffffffu, a1, off);
        cnt += __shfl_xor_sync(0xffffffffu, cnt, off);
    }
    if (lane == 0) {
        float inv = __frcp_rn(cnt + 1e-9f);
        float2 o = make_float2(a0 * inv + fcb[0], a1 * inv + fcb[1]);
        *(float2*)(out + row * 2) = o;
    }
}

extern "C" void kernel_launch(void* const* d_in, const int* in_sizes, int n_in,
                              void* d_out, int out_size)
{
    // metadata order: x, embed, Wi, bi, qw, Wo, bo, fcW, fcb
    const int*   x   = (const int*)  d_in[0];
    const float* qw  = (const float*)d_in[4];
    const float* Wo  = (const float*)d_in[5];
    const float* bo  = (const float*)d_in[6];
    const float* fcW = (const float*)d_in[7];
    const float* fcb = (const float*)d_in[8];
    float* out = (float*)d_out;

    qlstm_all<<<32, 1024>>>(x, qw, Wo, bo, fcW, fcb, out);

    (void)in_sizes; (void)n_in; (void)out_size;
}

// round 9
// speedup vs baseline: 1.2952x; 1.0037x over previous
#include <cuda_runtime.h>
#include <cuda_bf16.h>

__device__ __forceinline__ float tanh_(float x){ float y; asm("tanh.approx.f32 %0, %1;" : "=f"(y) : "f"(x)); return y; }
__device__ __forceinline__ float ex2_(float x) { float y; asm("ex2.approx.f32 %0, %1;" : "=f"(y) : "f"(x)); return y; }
__device__ __forceinline__ float lg2_(float x) { float y; asm("lg2.approx.f32 %0, %1;" : "=f"(y) : "f"(x)); return y; }
__device__ __forceinline__ float sig_(float x) { return __frcp_rn(1.0f + ex2_(-1.44269504f * x)); }

// Half-table scratch: g_half[pair][half][t] (values identical across replays).
__device__ float2 g_half[32][2][128];
// Per-pair monotonic tickets (padded to 128B): launch adds exactly 2 per pair.
__device__ unsigned g_tk[32][32];

// 64 blocks x 1024 threads. Blocks (2p,2p+1) form a pair sharing rows
// [32p,32p+32): each computes HALF the h-range of the (input-independent)
// s_t table, exchanges 1KB half-tables through L2 with a private 2-party
// ticket handshake, then both run stage2 (bitwise-identical duplicate writes).
__global__ void __launch_bounds__(1024, 1)
qlstm_all(const int*   __restrict__ x,    // (1024,128)
          const float* __restrict__ qw,   // (4,2,8)
          const float* __restrict__ Wo,   // (4,256,8)
          const float* __restrict__ bo,   // (4,256)
          const float* __restrict__ fcW,  // (2,256)
          const float* __restrict__ fcb,  // (2,)
          float*       __restrict__ out)  // (1024,2)
{
    const int tid  = threadIdx.x;
    const int lane = tid & 31;
    const int wrp  = tid >> 5;
    const int pair = blockIdx.x >> 1;
    const int half = blockIdx.x & 1;
    const int row  = pair * 32 + wrp;            // this warp's batch row

    __shared__ float4 pA[128];                   // (f, ig, A=ig/(1-f), log2 f) local h
    __shared__ float2 pB[128];                   // (oo*fcW0, oo*fcW1)
    __shared__ float2 s_s[128];                  // s_t (own half, then full)

    // Mask slice: issue immediately (L2-hot across replays; pair partner dedups).
    const int4 px = *(const int4*)(x + row * 128 + lane * 4);

    // ---- Param phase: warps 0..3, one h each (h = half*128 + tid).
    //      Loads issued first; zeta/zz via pure warp shuffles overlap them.
    if (tid < 128) {
        const int h = half * 128 + tid;
        float4 w0a = ((const float4*)(Wo + (0 * 256 + h) * 8))[0];
        float4 w0b = ((const float4*)(Wo + (0 * 256 + h) * 8))[1];
        float4 w1a = ((const float4*)(Wo + (1 * 256 + h) * 8))[0];
        float4 w1b = ((const float4*)(Wo + (1 * 256 + h) * 8))[1];
        float4 w2a = ((const float4*)(Wo + (2 * 256 + h) * 8))[0];
        float4 w2b = ((const float4*)(Wo + (2 * 256 + h) * 8))[1];
        float4 w3a = ((const float4*)(Wo + (3 * 256 + h) * 8))[0];
        float4 w3b = ((const float4*)(Wo + (3 * 256 + h) * 8))[1];
        float b0 = bo[0 * 256 + h], b1 = bo[1 * 256 + h];
        float b2 = bo[2 * 256 + h], b3 = bo[3 * 256 + h];
        float fc0 = fcW[h], fc1 = fcW[256 + h];

        // zeta on lane (g=lane>>3, j=lane&7); CNOT-ring products zz via shuffles.
        const int g_ = lane >> 3, j_ = lane & 7;
        const float zeta = -__sinf(qw[g_ * 16 + j_]);
        const int base = lane & 24;              // g*8
        float zzv = 1.0f;
#pragma unroll
        for (int j2 = 0; j2 < 8; j2++) {
            float zj = __shfl_sync(0xffffffffu, zeta, base + j2);
            bool incl = (j_ == 0) ? (j2 >= 1) : (j2 <= j_);
            zzv = incl ? zzv * zj : zzv;
        }
        // pre[g] = bo + Wo[g,h,:] . zz[g,:]
        float pre0 = b0, pre1 = b1, pre2 = b2, pre3 = b3;
#pragma unroll
        for (int q = 0; q < 4; q++) {
            float z0 = __shfl_sync(0xffffffffu, zzv,  0 + q);
            float z4 = __shfl_sync(0xffffffffu, zzv,  4 + q);
            float z8 = __shfl_sync(0xffffffffu, zzv,  8 + q);
            float z12= __shfl_sync(0xffffffffu, zzv, 12 + q);
            float z16= __shfl_sync(0xffffffffu, zzv, 16 + q);
            float z20= __shfl_sync(0xffffffffu, zzv, 20 + q);
            float z24= __shfl_sync(0xffffffffu, zzv, 24 + q);
            float z28= __shfl_sync(0xffffffffu, zzv, 28 + q);
            const float* a;
            a = (const float*)&w0a; pre0 += a[q] * z0;
            a = (const float*)&w0b; pre0 += a[q] * z4;
            a = (const float*)&w1a; pre1 += a[q] * z8;
            a = (const float*)&w1b; pre1 += a[q] * z12;
            a = (const float*)&w2a; pre2 += a[q] * z16;
            a = (const float*)&w2b; pre2 += a[q] * z20;
            a = (const float*)&w3a; pre3 += a[q] * z24;
            a = (const float*)&w3b; pre3 += a[q] * z28;
        }

        const float e   = ex2_(-1.44269504f * pre0);
        const float ope = 1.0f + e;
        const float f_  = __frcp_rn(ope);            // sigmoid(pre0)
        const float lf2 = -lg2_(ope);                // log2(f)
        const float ig_ = sig_(pre1) * tanh_(pre2);
        const float oo_ = sig_(pre3);
        const float omf = __fdividef(e, ope);        // 1 - f
        const float A_  = ig_ * __frcp_rn(omf);      // c_inf
        pA[tid] = make_float4(f_, ig_, A_, lf2);
        pB[tid] = make_float2(oo_ * fc0, oo_ * fc1);
    }
    __syncthreads();

    // ---- Sweep (half h-range): warp w owns t in [4w,4w+4); lane owns
    //      local h in {lane+32k}, k<4. Closed-form jump + 4 exact steps.
    {
        const float n0 = (float)(4 * wrp);
        float a00 = 0.f, a01 = 0.f, a02 = 0.f, a03 = 0.f;   // class 0
        float a10 = 0.f, a11 = 0.f, a12 = 0.f, a13 = 0.f;   // class 1
#pragma unroll
        for (int k = 0; k < 4; k++) {
            const int hl = lane + 32 * k;
            const float4 P = pA[hl];
            const float2 Q = pB[hl];
            float c = P.z - P.z * ex2_(n0 * P.w);
            float th;
            c = fmaf(P.x, c, P.y); th = tanh_(c); a00 += Q.x * th; a10 += Q.y * th;
            c = fmaf(P.x, c, P.y); th = tanh_(c); a01 += Q.x * th; a11 += Q.y * th;
            c = fmaf(P.x, c, P.y); th = tanh_(c); a02 += Q.x * th; a12 += Q.y * th;
            c = fmaf(P.x, c, P.y); th = tanh_(c); a03 += Q.x * th; a13 += Q.y * th;
        }
#pragma unroll
        for (int off = 16; off; off >>= 1) {
            a00 += __shfl_xor_sync(0xffffffffu, a00, off);
            a01 += __shfl_xor_sync(0xffffffffu, a01, off);
            a02 += __shfl_xor_sync(0xffffffffu, a02, off);
            a03 += __shfl_xor_sync(0xffffffffu, a03, off);
            a10 += __shfl_xor_sync(0xffffffffu, a10, off);
            a11 += __shfl_xor_sync(0xffffffffu, a11, off);
            a12 += __shfl_xor_sync(0xffffffffu, a12, off);
            a13 += __shfl_xor_sync(0xffffffffu, a13, off);
        }
        if (lane == 0) {
            float2 v0 = make_float2(a00, a10), v1 = make_float2(a01, a11);
            float2 v2 = make_float2(a02, a12), v3 = make_float2(a03, a13);
            s_s[4 * wrp + 0] = v0;  g_half[pair][half][4 * wrp + 0] = v0;
            s_s[4 * wrp + 1] = v1;  g_half[pair][half][4 * wrp + 1] = v1;
            s_s[4 * wrp + 2] = v2;  g_half[pair][half][4 * wrp + 2] = v2;
            s_s[4 * wrp + 3] = v3;  g_half[pair][half][4 * wrp + 3] = v3;
        }
    }
    __syncthreads();

    // ---- 2-party handshake on a private counter, then merge partner's half.
    if (tid == 0) {
        __threadfence();                               // publish g_half writes
        unsigned old    = atomicAdd(&g_tk[pair][0], 1u);
        unsigned target = ((old >> 1) + 1u) << 1;      // this launch's cohort end
        unsigned cur;
        do {
            asm volatile("ld.global.cg.u32 %0, [%1];" : "=r"(cur) : "l"(&g_tk[pair][0]));
        } while ((int)(cur - target) < 0);
        __threadfence();                               // acquire partner's data
    }
    __syncthreads();
    if (tid < 64) {                                    // 1KB partner half, float4
        const float4* src = (const float4*)&g_half[pair][half ^ 1][0];
        float4 p = __ldcg(&src[tid]);
        float4* s4 = (float4*)s_s;
        float4 m4 = s4[tid];
        s4[tid] = make_float4(m4.x + p.x, m4.y + p.y, m4.z + p.z, m4.w + p.w);
    }
    __syncthreads();

    // ---- Stage 2 (both pair members; identical results -> benign dup stores).
    const float4* st = (const float4*)s_s;
    float4 sa = st[lane * 2 + 0];
    float4 sb = st[lane * 2 + 1];
    float a0 = 0.0f, a1 = 0.0f, cnt = 0.0f, m;
    m = (px.x != 0) ? 1.0f : 0.0f; a0 += m * sa.x; a1 += m * sa.y; cnt += m;
    m = (px.y != 0) ? 1.0f : 0.0f; a0 += m * sa.z; a1 += m * sa.w; cnt += m;
    m = (px.z != 0) ? 1.0f : 0.0f; a0 += m * sb.x; a1 += m * sb.y; cnt += m;
    m = (px.w != 0) ? 1.0f : 0.0f; a0 += m * sb.z; a1 += m * sb.w; cnt += m;
#pragma unroll
    for (int off = 16; off; off >>= 1) {
        a0  += __shfl_xor_sync(0xffffffffu, a0, off);
        a1  += __shfl_xor_sync(0xffffffffu, a1, off);
        cnt += __shfl_xor_sync(0xffffffffu, cnt, off);
    }
    if (lane == 0) {
        float inv = __frcp_rn(cnt + 1e-9f);
        float2 o = make_float2(a0 * inv + fcb[0], a1 * inv + fcb[1]);
        *(float2*)(out + row * 2) = o;
    }
}

extern "C" void kernel_launch(void* const* d_in, const int* in_sizes, int n_in,
                              void* d_out, int out_size)
{
    // metadata order: x, embed, Wi, bi, qw, Wo, bo, fcW, fcb
    const int*   x   = (const int*)  d_in[0];
    const float* qw  = (const float*)d_in[4];
    const float* Wo  = (const float*)d_in[5];
    const float* bo  = (const float*)d_in[6];
    const float* fcW = (const float*)d_in[7];
    const float* fcb = (const float*)d_in[8];
    float* out = (float*)d_out;

    qlstm_all<<<64, 1024>>>(x, qw, Wo, bo, fcW, fcb, out);

    (void)in_sizes; (void)n_in; (void)out_size;
}